// round 4
// baseline (speedup 1.0000x reference)
#include <cuda_runtime.h>
#include <cuda_bf16.h>

#define D        1024
#define NBLK     6
#define NV       7            // 6 blocks + partial
#define THREADS  256
#define REPS     1e-6f
#define INV_SCALE (1.0f/32.0f)   // 1/(sqrt(1024)*temperature)

__global__ __launch_bounds__(THREADS)
void reskip_kernel(const float* __restrict__ blocks,
                   const float* __restrict__ partial,
                   const float* __restrict__ w_query,
                   const float* __restrict__ norm_w,
                   float* __restrict__ out,
                   int bt, long long blk_stride)
{
    const int tok  = blockIdx.x;
    const int tid  = threadIdx.x;
    const int j    = tid * 4;               // this thread's 4 channels
    const long long base = (long long)tok * D + j;

    // effective query = w_query * norm_weight (fp32)
    float4 q4  = *(const float4*)(w_query + j);
    float4 nw4 = *(const float4*)(norm_w  + j);
    float q[4] = { q4.x*nw4.x, q4.y*nw4.y, q4.z*nw4.z, q4.w*nw4.w };

    // Load all 7 vectors' slices into registers (single global pass)
    float x[NV][4];
    #pragma unroll
    for (int n = 0; n < NBLK; n++) {
        float4 v = *(const float4*)(blocks + (long long)n * blk_stride + base);
        x[n][0] = v.x; x[n][1] = v.y; x[n][2] = v.z; x[n][3] = v.w;
    }
    {
        float4 v = *(const float4*)(partial + base);
        x[6][0] = v.x; x[6][1] = v.y; x[6][2] = v.z; x[6][3] = v.w;
    }

    // Per-thread partial reductions: q.x and x.x per vector
    float qx[NV], xx[NV];
    #pragma unroll
    for (int n = 0; n < NV; n++) {
        float a = 0.f, s = 0.f;
        #pragma unroll
        for (int i = 0; i < 4; i++) {
            a = fmaf(q[i],    x[n][i], a);
            s = fmaf(x[n][i], x[n][i], s);
        }
        qx[n] = a; xx[n] = s;
    }

    // Warp shuffle tree
    #pragma unroll
    for (int n = 0; n < NV; n++) {
        #pragma unroll
        for (int off = 16; off > 0; off >>= 1) {
            qx[n] += __shfl_xor_sync(0xffffffffu, qx[n], off);
            xx[n] += __shfl_xor_sync(0xffffffffu, xx[n], off);
        }
    }

    __shared__ float s_qx[NV][8];
    __shared__ float s_xx[NV][8];
    __shared__ float s_coef[NV];   // c[0..5] = phase1_weight*exp_s[n], c[6] = partial_weight
    const int warp = tid >> 5, lane = tid & 31;
    if (lane == 0) {
        #pragma unroll
        for (int n = 0; n < NV; n++) { s_qx[n][warp] = qx[n]; s_xx[n][warp] = xx[n]; }
    }
    __syncthreads();

    if (tid == 0) {
        // Final scores
        float sc[NV];
        #pragma unroll
        for (int n = 0; n < NV; n++) {
            float a = 0.f, s = 0.f;
            #pragma unroll
            for (int w = 0; w < 8; w++) { a += s_qx[n][w]; s += s_xx[n][w]; }
            float inv = rsqrtf(s * (1.0f / (float)D) + REPS);
            sc[n] = a * inv * INV_SCALE;
        }

        // Phase-1 softmax over the 6 completed blocks
        float m1 = sc[0];
        #pragma unroll
        for (int n = 1; n < NBLK; n++) m1 = fmaxf(m1, sc[n]);
        float es[NBLK], lse = 0.f;
        #pragma unroll
        for (int n = 0; n < NBLK; n++) { es[n] = expf(sc[n] - m1); lse += es[n]; }
        float logl = logf(lse);
        float ent1 = 0.f;
        #pragma unroll
        for (int n = 0; n < NBLK; n++)
            ent1 -= (es[n] / lse) * ((sc[n] - m1) - logl);

        // Online-softmax merge with partial block
        float ps    = sc[6];
        float mm    = fmaxf(m1, ps);
        float c1    = expf(m1 - mm);
        float cp    = expf(ps - mm);
        float denom = c1 * lse + cp;
        float w1w   = c1 * lse / denom;     // phase1_weight
        float pw    = cp / denom;           // partial_weight

        #pragma unroll
        for (int n = 0; n < NBLK; n++) s_coef[n] = w1w * es[n];
        s_coef[6] = pw;

        float w1c = fmaxf(w1w, 1e-8f);
        float wpc = fmaxf(pw,  1e-8f);
        out[(long long)bt * D + tok] = w1c * ent1 - w1c * logf(w1c) - wpc * logf(wpc);
    }
    __syncthreads();

    float c[NV];
    #pragma unroll
    for (int n = 0; n < NV; n++) c[n] = s_coef[n];

    // hidden = phase1_weight * sum_n exp_s[n]*x_n  +  partial_weight * partial
    float o0 = 0.f, o1 = 0.f, o2 = 0.f, o3 = 0.f;
    #pragma unroll
    for (int n = 0; n < NV; n++) {
        o0 = fmaf(c[n], x[n][0], o0);
        o1 = fmaf(c[n], x[n][1], o1);
        o2 = fmaf(c[n], x[n][2], o2);
        o3 = fmaf(c[n], x[n][3], o3);
    }
    float4 ov = make_float4(o0, o1, o2, o3);
    *(float4*)(out + base) = ov;
}

extern "C" void kernel_launch(void* const* d_in, const int* in_sizes, int n_in,
                              void* d_out, int out_size)
{
    const float* blocks  = (const float*)d_in[0];   // [6, b, t, d]
    const float* partial = (const float*)d_in[1];   // [b, t, d]
    const float* wq      = (const float*)d_in[2];   // [d]
    const float* nw      = (const float*)d_in[3];   // [d]
    float* out           = (float*)d_out;           // [b*t*d hidden][b*t entropy]

    int bt = in_sizes[1] / D;                       // b*t tokens
    long long blk_stride = (long long)in_sizes[0] / NBLK;  // b*t*d

    reskip_kernel<<<bt, THREADS>>>(blocks, partial, wq, nw, out, bt, blk_stride);
}

// round 5
// speedup vs baseline: 1.0379x; 1.0379x over previous
#include <cuda_runtime.h>
#include <cuda_bf16.h>

#define D        1024
#define NBLK     6
#define NV       7            // 6 blocks + partial
#define THREADS  256
#define REPS     1e-6f
#define INV_SCALE (1.0f/32.0f)   // 1/(sqrt(1024)*temperature)

__global__ __launch_bounds__(THREADS, 6)
void reskip_kernel(const float* __restrict__ blocks,
                   const float* __restrict__ partial,
                   const float* __restrict__ w_query,
                   const float* __restrict__ norm_w,
                   float* __restrict__ out,
                   int bt, long long blk_stride)
{
    __shared__ float s_x[NV][D];        // 28 KB token data staging
    __shared__ float s_qx[NV][8];
    __shared__ float s_xx[NV][8];
    __shared__ float s_coef[NV];        // c[0..5]=w1*exp_s[n], c[6]=partial_weight

    const int tok  = blockIdx.x;
    const int tid  = threadIdx.x;
    const int j    = tid * 4;               // this thread's 4 channels
    const long long base = (long long)tok * D + j;

    // effective query = w_query * norm_weight (fp32); hot in L2/L1 after wave 1
    float4 q4  = *(const float4*)(w_query + j);
    float4 nw4 = *(const float4*)(norm_w  + j);
    const float q0 = q4.x*nw4.x, q1 = q4.y*nw4.y, q2 = q4.z*nw4.z, q3 = q4.w*nw4.w;

    // Single global pass: load, accumulate partials, park data in smem.
    float qx[NV], xx[NV];
    #pragma unroll
    for (int n = 0; n < NV; n++) {
        float4 v;
        if (n < NBLK)
            v = *(const float4*)(blocks + (long long)n * blk_stride + base);
        else
            v = *(const float4*)(partial + base);

        float a, s;
        a = q0 * v.x;        s = v.x * v.x;
        a = fmaf(q1, v.y, a); s = fmaf(v.y, v.y, s);
        a = fmaf(q2, v.z, a); s = fmaf(v.z, v.z, s);
        a = fmaf(q3, v.w, a); s = fmaf(v.w, v.w, s);
        qx[n] = a; xx[n] = s;

        *(float4*)(&s_x[n][j]) = v;   // transient regs -> smem
    }

    // Warp shuffle tree
    #pragma unroll
    for (int n = 0; n < NV; n++) {
        #pragma unroll
        for (int off = 16; off > 0; off >>= 1) {
            qx[n] += __shfl_xor_sync(0xffffffffu, qx[n], off);
            xx[n] += __shfl_xor_sync(0xffffffffu, xx[n], off);
        }
    }

    const int warp = tid >> 5, lane = tid & 31;
    if (lane == 0) {
        #pragma unroll
        for (int n = 0; n < NV; n++) { s_qx[n][warp] = qx[n]; s_xx[n][warp] = xx[n]; }
    }
    __syncthreads();

    if (tid == 0) {
        // Final scores
        float sc[NV];
        #pragma unroll
        for (int n = 0; n < NV; n++) {
            float a = 0.f, s = 0.f;
            #pragma unroll
            for (int w = 0; w < 8; w++) { a += s_qx[n][w]; s += s_xx[n][w]; }
            float inv = rsqrtf(s * (1.0f / (float)D) + REPS);
            sc[n] = a * inv * INV_SCALE;
        }

        // Phase-1 softmax over the 6 completed blocks
        float m1 = sc[0];
        #pragma unroll
        for (int n = 1; n < NBLK; n++) m1 = fmaxf(m1, sc[n]);
        float es[NBLK], lse = 0.f;
        #pragma unroll
        for (int n = 0; n < NBLK; n++) { es[n] = expf(sc[n] - m1); lse += es[n]; }
        float logl = logf(lse);
        float ent1 = 0.f;
        #pragma unroll
        for (int n = 0; n < NBLK; n++)
            ent1 -= (es[n] / lse) * ((sc[n] - m1) - logl);

        // Online-softmax merge with partial block
        float ps    = sc[6];
        float mm    = fmaxf(m1, ps);
        float c1    = expf(m1 - mm);
        float cp    = expf(ps - mm);
        float denom = c1 * lse + cp;
        float w1w   = c1 * lse / denom;     // phase1_weight
        float pw    = cp / denom;           // partial_weight

        #pragma unroll
        for (int n = 0; n < NBLK; n++) s_coef[n] = w1w * es[n];
        s_coef[6] = pw;

        float w1c = fmaxf(w1w, 1e-8f);
        float wpc = fmaxf(pw,  1e-8f);
        out[(long long)bt * D + tok] = w1c * ent1 - w1c * logf(w1c) - wpc * logf(wpc);
    }
    __syncthreads();

    // hidden = sum_n c[n] * x_n   (data re-read from smem, conflict-free)
    float c[NV];
    #pragma unroll
    for (int n = 0; n < NV; n++) c[n] = s_coef[n];

    float o0 = 0.f, o1 = 0.f, o2 = 0.f, o3 = 0.f;
    #pragma unroll
    for (int n = 0; n < NV; n++) {
        float4 v = *(const float4*)(&s_x[n][j]);
        o0 = fmaf(c[n], v.x, o0);
        o1 = fmaf(c[n], v.y, o1);
        o2 = fmaf(c[n], v.z, o2);
        o3 = fmaf(c[n], v.w, o3);
    }
    *(float4*)(out + base) = make_float4(o0, o1, o2, o3);
}

extern "C" void kernel_launch(void* const* d_in, const int* in_sizes, int n_in,
                              void* d_out, int out_size)
{
    const float* blocks  = (const float*)d_in[0];   // [6, b, t, d]
    const float* partial = (const float*)d_in[1];   // [b, t, d]
    const float* wq      = (const float*)d_in[2];   // [d]
    const float* nw      = (const float*)d_in[3];   // [d]
    float* out           = (float*)d_out;           // [b*t*d hidden][b*t entropy]

    int bt = in_sizes[1] / D;                       // b*t tokens
    long long blk_stride = (long long)in_sizes[0] / NBLK;  // b*t*d

    reskip_kernel<<<bt, THREADS>>>(blocks, partial, wq, nw, out, bt, blk_stride);
}